// round 10
// baseline (speedup 1.0000x reference)
#include <cuda_runtime.h>
#include <math.h>

// Problem constants
#define TT    1024
#define DIMX  1024
#define HH    8
#define DK    192
#define DV    128
#define QLR   768
#define KVLR  512
#define DROPE 64

// Stage-1 concatenated layout (columns of big buffer):
//   [0,768) qa | [768,1344) kva (k_pe at 1280) | [1344,2880) eg | [2880,2888) beta | pad
#define NBIG 2944

// ---------------- scratch ----------------
__device__ float d_bc  [DIMX * NBIG];
__device__ float d_big [TT * NBIG];
__device__ float d_qn  [TT * QLR];
__device__ float d_kvn [TT * KVLR];
__device__ float d_q   [TT * HH * DK];
__device__ float d_kv  [TT * HH * 256];
__device__ float d_kf  [TT * HH * DK];
__device__ float d_ov  [TT * HH * DV];

// ================= TF32 tensor-core GEMM (double-buffered, cp.async B) =================
#define BM 64
#define BN 128
#define BK 16

__device__ __forceinline__ unsigned f2tf(float f) {
    unsigned u;
    asm("cvt.rna.tf32.f32 %0, %1;" : "=r"(u) : "f"(f));
    return u;
}

__device__ __forceinline__ void mma_tf32(float* c, const unsigned* a, const unsigned* b) {
    asm volatile(
        "mma.sync.aligned.m16n8k8.row.col.f32.tf32.tf32.f32 "
        "{%0,%1,%2,%3}, {%4,%5,%6,%7}, {%8,%9}, {%0,%1,%2,%3};\n"
        : "+f"(c[0]), "+f"(c[1]), "+f"(c[2]), "+f"(c[3])
        : "r"(a[0]), "r"(a[1]), "r"(a[2]), "r"(a[3]), "r"(b[0]), "r"(b[1]));
}

__device__ __forceinline__ void cp16(float* dst, const float* src) {
    unsigned s = (unsigned)__cvta_generic_to_shared(dst);
    asm volatile("cp.async.ca.shared.global [%0], [%1], 16;\n" :: "r"(s), "l"(src));
}
__device__ __forceinline__ void cp4(float* dst, const float* src) {
    unsigned s = (unsigned)__cvta_generic_to_shared(dst);
    asm volatile("cp.async.ca.shared.global [%0], [%1], 4;\n" :: "r"(s), "l"(src));
}
#define CP_COMMIT() asm volatile("cp.async.commit_group;\n" ::: "memory")
#define CP_WAIT0()  asm volatile("cp.async.wait_group 0;\n" ::: "memory")
#define CP_WAITG(n) asm volatile("cp.async.wait_group %0;\n" :: "n"(n) : "memory")

// EPI: 0 none, 1 = stage-1 epilogue (sigmoid for g/beta column ranges)
__device__ __forceinline__ float epi1(float v, int gc, const float* __restrict__ bias) {
    if (gc >= 1344 && gc < 2888) {
        float b = (gc < 2880) ? bias[gc - 1344] : 0.f;
        v = 1.f / (1.f + expf(-(v + b)));
    }
    return v;
}

// smem raw fp32 (A transposed+swizzled, B swizzled); cvt.rna.tf32 at fragment load.
template <int EPI>
__device__ __forceinline__ void tgemm_core(int N, int K,
                                           const float* __restrict__ A, int lda,
                                           const float* __restrict__ B, int ldb,
                                           const float* __restrict__ bias,
                                           float* __restrict__ C, int ldc,
                                           float* sA, float* sB) {
    const int tid  = threadIdx.x;             // 256 threads = 8 warps
    const int crow = blockIdx.y * BM;
    const int ccol = blockIdx.x * BN;

    const int wid  = tid >> 5;
    const int lane = tid & 31;
    const int lq   = lane >> 2;
    const int lr   = lane & 3;
    const int rm   = (wid & 1) * 32;   // 2 warps in M
    const int cn   = (wid >> 1) * 32;  // 4 warps in N

    const int am  = tid >> 2;          // 0..63
    const int ak4 = (tid & 3) * 4;     // 0,4,8,12
    const int bk  = tid >> 4;          // 0..15
    const int bc8 = (tid & 15) * 8;    // 0..120
    const int swb = (((bk & 3) ^ ((bk >> 2) & 3)) << 3);

    float acc[2][4][4] = {};
    float4 aR;

    // ---- prologue: tile 0 ----
    aR = *reinterpret_cast<const float4*>(&A[(long)(crow + am) * lda + ak4]);
    cp16(&sB[bk * BN + ((bc8) ^ swb)],     &B[(long)bk * ldb + ccol + bc8]);
    cp16(&sB[bk * BN + ((bc8 + 4) ^ swb)], &B[(long)bk * ldb + ccol + bc8 + 4]);
    CP_COMMIT();
    {
        const float av[4] = {aR.x, aR.y, aR.z, aR.w};
        #pragma unroll
        for (int i = 0; i < 4; ++i) {
            const int k  = ak4 + i;
            const int sw = (((k & 3) ^ ((k >> 2) & 3)) << 3);
            sA[k * BM + (am ^ sw)] = av[i];
        }
    }
    if (K > BK)
        aR = *reinterpret_cast<const float4*>(&A[(long)(crow + am) * lda + BK + ak4]);
    CP_WAIT0();
    __syncthreads();

    int buf = 0;
    for (int k0 = 0; k0 < K; k0 += BK, buf ^= 1) {
        float* cA = sA + buf * (BK * BM);
        float* cB = sB + buf * (BK * BN);
        const int nxt = buf ^ 1;

        // ---- issue next tile into the other buffer ----
        if (k0 + BK < K) {
            float* nB = sB + nxt * (BK * BN);
            cp16(&nB[bk * BN + ((bc8) ^ swb)],     &B[(long)(k0 + BK + bk) * ldb + ccol + bc8]);
            cp16(&nB[bk * BN + ((bc8 + 4) ^ swb)], &B[(long)(k0 + BK + bk) * ldb + ccol + bc8 + 4]);
            CP_COMMIT();
            float* nA = sA + nxt * (BK * BM);
            const float av[4] = {aR.x, aR.y, aR.z, aR.w};
            #pragma unroll
            for (int i = 0; i < 4; ++i) {
                const int k  = ak4 + i;
                const int sw = (((k & 3) ^ ((k >> 2) & 3)) << 3);
                nA[k * BM + (am ^ sw)] = av[i];
            }
            if (k0 + 2 * BK < K)
                aR = *reinterpret_cast<const float4*>(&A[(long)(crow + am) * lda + k0 + 2 * BK + ak4]);
        }

        // ---- compute on current buffer ----
        #pragma unroll
        for (int k8 = 0; k8 < BK; k8 += 8) {
            const int f0 = ((lr ^ (k8 >> 2)) & 3) << 3;
            const int f1 = f0 ^ 8;
            unsigned af[2][4], bf[4][2];
            #pragma unroll
            for (int mt = 0; mt < 2; ++mt) {
                const int r = rm + mt * 16 + lq;
                af[mt][0] = f2tf(cA[(k8 + lr) * BM + (r ^ f0)]);
                af[mt][1] = f2tf(cA[(k8 + lr) * BM + ((r + 8) ^ f0)]);
                af[mt][2] = f2tf(cA[(k8 + lr + 4) * BM + (r ^ f1)]);
                af[mt][3] = f2tf(cA[(k8 + lr + 4) * BM + ((r + 8) ^ f1)]);
            }
            #pragma unroll
            for (int nt = 0; nt < 4; ++nt) {
                const int c = cn + nt * 8 + lq;
                bf[nt][0] = f2tf(cB[(k8 + lr) * BN + (c ^ f0)]);
                bf[nt][1] = f2tf(cB[(k8 + lr + 4) * BN + (c ^ f1)]);
            }
            #pragma unroll
            for (int mt = 0; mt < 2; ++mt)
                #pragma unroll
                for (int nt = 0; nt < 4; ++nt)
                    mma_tf32(acc[mt][nt], af[mt], bf[nt]);
        }
        CP_WAIT0();
        __syncthreads();
    }

    #pragma unroll
    for (int mt = 0; mt < 2; ++mt) {
        const int row = crow + rm + mt * 16 + lq;
        #pragma unroll
        for (int nt = 0; nt < 4; ++nt) {
            const int col = ccol + cn + nt * 8 + lr * 2;
            float v0 = acc[mt][nt][0], v1 = acc[mt][nt][1];
            float v2 = acc[mt][nt][2], v3 = acc[mt][nt][3];
            if (EPI == 1) {
                v0 = epi1(v0, col, bias);     v1 = epi1(v1, col + 1, bias);
                v2 = epi1(v2, col, bias);     v3 = epi1(v3, col + 1, bias);
            }
            *reinterpret_cast<float2*>(&C[(long)row * ldc + col])       = make_float2(v0, v1);
            *reinterpret_cast<float2*>(&C[(long)(row + 8) * ldc + col]) = make_float2(v2, v3);
        }
    }
}

template <int EPI>
__global__ __launch_bounds__(256, 2)
void tgemm_kernel(int N, int K, const float* __restrict__ A, int lda,
                  const float* __restrict__ B, int ldb,
                  const float* __restrict__ bias, float* __restrict__ C, int ldc) {
    __shared__ float sA[2 * BK * BM];
    __shared__ float sB[2 * BK * BN];
    tgemm_core<EPI>(N, K, A, lda, B, ldb, bias, C, ldc, sA, sB);
}

__global__ __launch_bounds__(256, 2)
void tgemm_dual_kernel(int N0, int K0, const float* __restrict__ A0,
                       const float* __restrict__ B0, float* __restrict__ C0,
                       int N1, int K1, const float* __restrict__ A1,
                       const float* __restrict__ B1, float* __restrict__ C1) {
    __shared__ float sA[2 * BK * BM];
    __shared__ float sB[2 * BK * BN];
    if (blockIdx.z == 0) {
        if ((int)blockIdx.x * BN >= N0) return;
        tgemm_core<0>(N0, K0, A0, K0, B0, N0, nullptr, C0, N0, sA, sB);
    } else {
        tgemm_core<0>(N1, K1, A1, K1, B1, N1, nullptr, C1, N1, sA, sB);
    }
}

// ---------------- stage-1 weight concat ----------------
__global__ void concat_w(const float* __restrict__ wq_a,
                         const float* __restrict__ wkv_a,
                         const float* __restrict__ wg_w,
                         const float* __restrict__ wb,
                         float* __restrict__ Bc) {
    const int c = blockIdx.x * 128 + threadIdx.x;
    const int r = blockIdx.y;
    float v;
    if      (c < 768)  v = wq_a [r * 768  + c];
    else if (c < 1344) v = wkv_a[r * 576  + (c - 768)];
    else if (c < 2880) v = wg_w [r * 1536 + (c - 1344)];
    else if (c < 2888) v = wb   [r * 8    + (c - 2880)];
    else               v = 0.f;
    Bc[(long)r * NBIG + c] = v;
}

// ---------------- fused row RMS norms (q then kv) ----------------
__device__ __forceinline__ void rms_row(const float* __restrict__ row,
                                        const float* __restrict__ w,
                                        float* __restrict__ out, int n) {
    float ss = 0.f;
    for (int i = threadIdx.x; i < n; i += 256) {
        float v = row[i];
        ss += v * v;
    }
    #pragma unroll
    for (int off = 16; off; off >>= 1)
        ss += __shfl_xor_sync(0xffffffffu, ss, off);
    __shared__ float red[8];
    __shared__ float scale_s;
    const int wid = threadIdx.x >> 5;
    if ((threadIdx.x & 31) == 0) red[wid] = ss;
    __syncthreads();
    if (threadIdx.x == 0) {
        float tot = 0.f;
        #pragma unroll
        for (int i = 0; i < 8; ++i) tot += red[i];
        scale_s = rsqrtf(tot / (float)n + 1e-5f);
    }
    __syncthreads();
    const float sc = scale_s;
    for (int i = threadIdx.x; i < n; i += 256)
        out[i] = row[i] * sc * w[i];
    __syncthreads();   // shared red/scale reused by second call
}

__global__ void rms_fused(const float* __restrict__ big,
                          const float* __restrict__ qw,
                          const float* __restrict__ kvw,
                          float* __restrict__ qn,
                          float* __restrict__ kvn) {
    const int t = blockIdx.x;
    rms_row(big + (long)t * NBIG,       qw,  qn  + (long)t * QLR,  QLR);
    rms_row(big + (long)t * NBIG + 768, kvw, kvn + (long)t * KVLR, KVLR);
}

// ---------------- prep: l2norm q (in place, *DK^-0.5), build + l2norm k ----------------
__global__ void prep_kernel(float* __restrict__ q,
                            const float* __restrict__ kv,
                            const float* __restrict__ big,
                            float* __restrict__ kf) {
    const int t = blockIdx.x >> 3;
    const int h = blockIdx.x & 7;
    const int i = threadIdx.x;  // 0..191

    const int qidx = t * (HH * DK) + h * DK + i;
    const float qv = q[qidx];
    const float kvv = (i < 128) ? kv[t * (HH * 256) + h * 256 + i]
                                : big[(long)t * NBIG + 1280 + (i - 128)];

    float q2 = qv * qv, k2 = kvv * kvv;
    #pragma unroll
    for (int off = 16; off; off >>= 1) {
        q2 += __shfl_xor_sync(0xffffffffu, q2, off);
        k2 += __shfl_xor_sync(0xffffffffu, k2, off);
    }
    __shared__ float sq[6], sk[6];
    __shared__ float scl[2];
    const int wid = threadIdx.x >> 5;
    if ((threadIdx.x & 31) == 0) { sq[wid] = q2; sk[wid] = k2; }
    __syncthreads();
    if (threadIdx.x == 0) {
        float a = 0.f, b = 0.f;
        #pragma unroll
        for (int j = 0; j < 6; ++j) { a += sq[j]; b += sk[j]; }
        scl[0] = rsqrtf(a + 1e-6f) * 0.07216878364870322f;
        scl[1] = rsqrtf(b + 1e-6f);
    }
    __syncthreads();
    q[qidx] = qv * scl[0];
    kf[qidx] = kvv * scl[1];
}

// ---------------- KDA recurrence: smem-staged, cp.async 8-deep pipeline ----------------
// Block = one head-slice: h = blockIdx.x>>4, v columns (blockIdx.x&15)*8 .. +7 (warp per v).
// Per step, block stages e/k/q rows (192 floats each), 8 v values, beta into a 9-slot ring.
// IMPORTANT: slot index must come from the UNWRAPPED step (1024 % 9 != 0); past-the-end
// issues are skipped but still commit an (empty) group so wait_group counting stays aligned.
#define RD     8                 // prefetch depth (steps ahead)
#define RSLOTS (RD + 1)
#define SLOT_F 592               // floats/slot: 3*192 + 8 (v) + 1 (bt), padded

struct RecIn {
    float2 e0, e1, e2, k0, k1, k2, q0, q1, q2;
    float vt, bt;
};

__global__ __launch_bounds__(256)
void kda_rec(const float* __restrict__ qf,   // [T, 1536]
             const float* __restrict__ kf,   // [T, 1536]
             const float* __restrict__ big,  // eg at 1344, beta at 2880
             const float* __restrict__ kv,   // [T, 2048], v at h*256+128
             float* __restrict__ o) {        // [T, 1024]
    __shared__ float sbuf[RSLOTS * SLOT_F];

    const int tid   = threadIdx.x;
    const int wid   = tid >> 5;
    const int lane  = tid & 31;
    const int h     = blockIdx.x >> 4;
    const int vbase = (blockIdx.x & 15) * 8;
    const int v     = vbase + wid;
    const int lane6 = lane * 6;

    #define ISSUE(tstep) do {                                                        \
        const int _t = (tstep);                                                      \
        if (_t < TT) {                                                               \
            float* sl = sbuf + (_t % RSLOTS) * SLOT_F;                               \
            if (tid < 48)                                                            \
                cp16(sl + tid * 4,              big + (long)_t * NBIG + 1344 + h * 192 + tid * 4); \
            else if (tid < 96)                                                       \
                cp16(sl + 192 + (tid - 48) * 4, kf + (long)_t * 1536 + h * 192 + (tid - 48) * 4);  \
            else if (tid < 144)                                                      \
                cp16(sl + 384 + (tid - 96) * 4, qf + (long)_t * 1536 + h * 192 + (tid - 96) * 4);  \
            else if (tid < 146)                                                      \
                cp16(sl + 576 + (tid - 144) * 4, kv + (long)_t * 2048 + h * 256 + 128 + vbase + (tid - 144) * 4); \
            else if (tid == 146)                                                     \
                cp4(sl + 584,                   big + (long)_t * NBIG + 2880 + h);   \
        }                                                                            \
        CP_COMMIT();                                                                 \
    } while (0)

    #define RLOADS(I, tstep) do {                                                    \
        const float* Sp = sbuf + ((tstep) % RSLOTS) * SLOT_F;                        \
        const float* ep = Sp + lane6;                                                \
        (I).e0 = *(const float2*)(ep);        (I).e1 = *(const float2*)(ep + 2);     \
        (I).e2 = *(const float2*)(ep + 4);                                           \
        (I).k0 = *(const float2*)(ep + 192);  (I).k1 = *(const float2*)(ep + 194);   \
        (I).k2 = *(const float2*)(ep + 196);                                         \
        (I).q0 = *(const float2*)(ep + 384);  (I).q1 = *(const float2*)(ep + 386);   \
        (I).q2 = *(const float2*)(ep + 388);                                         \
        (I).vt = Sp[576 + wid];                                                      \
        (I).bt = Sp[584];                                                            \
    } while (0)

    #define RSTEP(I, t) do {                                                         \
        s0 *= (I).e0.x; s1 *= (I).e0.y; s2 *= (I).e1.x;                              \
        s3 *= (I).e1.y; s4 *= (I).e2.x; s5 *= (I).e2.y;                              \
        float kse = fmaf(s0, (I).k0.x, fmaf(s1, (I).k0.y, fmaf(s2, (I).k1.x,         \
                    fmaf(s3, (I).k1.y, fmaf(s4, (I).k2.x, s5 * (I).k2.y)))));        \
        float qse = fmaf(s0, (I).q0.x, fmaf(s1, (I).q0.y, fmaf(s2, (I).q1.x,         \
                    fmaf(s3, (I).q1.y, fmaf(s4, (I).q2.x, s5 * (I).q2.y)))));        \
        float qk  = fmaf((I).k0.x, (I).q0.x, fmaf((I).k0.y, (I).q0.y,                \
                    fmaf((I).k1.x, (I).q1.x, fmaf((I).k1.y, (I).q1.y,                \
                    fmaf((I).k2.x, (I).q2.x, (I).k2.y * (I).q2.y)))));               \
        _Pragma("unroll")                                                            \
        for (int off = 16; off; off >>= 1) {                                         \
            kse += __shfl_xor_sync(0xffffffffu, kse, off);                           \
            qse += __shfl_xor_sync(0xffffffffu, qse, off);                           \
            qk  += __shfl_xor_sync(0xffffffffu, qk,  off);                           \
        }                                                                            \
        const float u = (I).bt * ((I).vt - kse);                                     \
        float ov = fmaf(qk, u, qse);                                                 \
        s0 = fmaf((I).k0.x, u, s0); s1 = fmaf((I).k0.y, u, s1);                      \
        s2 = fmaf((I).k1.x, u, s2); s3 = fmaf((I).k1.y, u, s3);                      \
        s4 = fmaf((I).k2.x, u, s4); s5 = fmaf((I).k2.y, u, s5);                      \
        if (lane == 0) {                                                             \
            if (ov != ov) ov = 0.f;                                                  \
            ov = fminf(fmaxf(ov, -10000.f), 10000.f);                                \
            o[(t) * (HH * DV) + h * DV + v] = ov;                                    \
        }                                                                            \
    } while (0)

    float s0 = 0.f, s1 = 0.f, s2 = 0.f, s3 = 0.f, s4 = 0.f, s5 = 0.f;

    // prologue: fill RD slots (groups for steps 0..RD-1)
    for (int s = 0; s < RD; ++s) ISSUE(s);
    CP_WAITG(RD - 1);   // step-0 group complete
    __syncthreads();

    RecIn ia, ib;
    RLOADS(ia, 0);

    for (int t = 0; t < TT; t += 2) {
        ISSUE(t + RD);
        CP_WAITG(RD - 1);                 // step t+1 group complete
        __syncthreads();
        RLOADS(ib, t + 1);
        RSTEP(ia, t);

        ISSUE(t + 1 + RD);
        CP_WAITG(RD - 1);                 // step t+2 group complete
        __syncthreads();
        if (t + 2 < TT) RLOADS(ia, t + 2);
        RSTEP(ib, t + 1);
    }
    #undef ISSUE
    #undef RLOADS
    #undef RSTEP
}

// ---------------- launch ----------------
extern "C" void kernel_launch(void* const* d_in, const int* in_sizes, int n_in,
                              void* d_out, int out_size) {
    (void)in_sizes; (void)n_in; (void)out_size;
    const float* x         = (const float*)d_in[0];
    const float* wq_a      = (const float*)d_in[3];
    const float* q_norm_w  = (const float*)d_in[4];
    const float* wq_b      = (const float*)d_in[5];
    const float* wkv_a     = (const float*)d_in[6];
    const float* kv_norm_w = (const float*)d_in[7];
    const float* wkv_b     = (const float*)d_in[8];
    const float* wg_w      = (const float*)d_in[9];
    const float* wg_b      = (const float*)d_in[10];
    const float* wb        = (const float*)d_in[11];
    const float* wo        = (const float*)d_in[12];
    float* out = (float*)d_out;

    float *bc, *big, *qn, *kvn, *q, *kv, *kf, *ov;
    cudaGetSymbolAddress((void**)&bc,  d_bc);
    cudaGetSymbolAddress((void**)&big, d_big);
    cudaGetSymbolAddress((void**)&qn,  d_qn);
    cudaGetSymbolAddress((void**)&kvn, d_kvn);
    cudaGetSymbolAddress((void**)&q,   d_q);
    cudaGetSymbolAddress((void**)&kv,  d_kv);
    cudaGetSymbolAddress((void**)&kf,  d_kf);
    cudaGetSymbolAddress((void**)&ov,  d_ov);

    concat_w<<<dim3(NBIG / 128, DIMX), 128>>>(wq_a, wkv_a, wg_w, wb, bc);

    // Stage 1: big = x @ [wq_a | wkv_a | wg_w | wb] (+ sigmoid epilogues)
    tgemm_kernel<1><<<dim3(NBIG / BN, TT / BM), 256>>>(NBIG, DIMX, x, DIMX, bc, NBIG, wg_b, big, NBIG);

    // Stage 2: fused RMS norms
    rms_fused<<<TT, 256>>>(big, q_norm_w, kv_norm_w, qn, kvn);

    // Stage 3: batched up-projections
    tgemm_dual_kernel<<<dim3(2048 / BN, TT / BM, 2), 256>>>(
        1536, QLR,  qn,  wq_b,  q,
        2048, KVLR, kvn, wkv_b, kv);

    // Stage 4: l2norm q/k, assemble k
    prep_kernel<<<TT * HH, 192>>>(q, kv, big, kf);

    // Stage 5: sequential KDA recurrence (smem-staged pipeline)
    kda_rec<<<128, 256>>>(q, kf, big, kv, ov);

    // Stage 6: output projection (plain TF32)
    tgemm_kernel<0><<<dim3(DIMX / BN, TT / BM), 256>>>(DIMX, DIMX, ov, DIMX, wo, DIMX, nullptr, out, DIMX);
}

// round 11
// speedup vs baseline: 1.1593x; 1.1593x over previous
#include <cuda_runtime.h>
#include <math.h>

// Problem constants
#define TT    1024
#define DIMX  1024
#define HH    8
#define DK    192
#define DV    128
#define QLR   768
#define KVLR  512
#define DROPE 64

// Stage-1 concatenated layout (columns of big buffer):
//   [0,768) qa | [768,1344) kva (k_pe at 1280) | [1344,2880) eg | [2880,2888) beta | pad
#define NBIG 2944

// ---------------- scratch ----------------
__device__ float d_bc  [DIMX * NBIG];
__device__ float d_big [TT * NBIG];
__device__ float d_qn  [TT * QLR];
__device__ float d_kvn [TT * KVLR];
__device__ float d_q   [TT * HH * DK];
__device__ float d_kv  [TT * HH * 256];
__device__ float d_kf  [TT * HH * DK];
__device__ float d_ov  [TT * HH * DV];

// ================= TF32 tensor-core GEMM (double-buffered, cp.async B) =================
#define BM 64
#define BN 128
#define BK 16

__device__ __forceinline__ unsigned f2tf(float f) {
    unsigned u;
    asm("cvt.rna.tf32.f32 %0, %1;" : "=r"(u) : "f"(f));
    return u;
}

__device__ __forceinline__ void mma_tf32(float* c, const unsigned* a, const unsigned* b) {
    asm volatile(
        "mma.sync.aligned.m16n8k8.row.col.f32.tf32.tf32.f32 "
        "{%0,%1,%2,%3}, {%4,%5,%6,%7}, {%8,%9}, {%0,%1,%2,%3};\n"
        : "+f"(c[0]), "+f"(c[1]), "+f"(c[2]), "+f"(c[3])
        : "r"(a[0]), "r"(a[1]), "r"(a[2]), "r"(a[3]), "r"(b[0]), "r"(b[1]));
}

__device__ __forceinline__ void cp16(float* dst, const float* src) {
    unsigned s = (unsigned)__cvta_generic_to_shared(dst);
    asm volatile("cp.async.ca.shared.global [%0], [%1], 16;\n" :: "r"(s), "l"(src));
}
#define CP_COMMIT() asm volatile("cp.async.commit_group;\n" ::: "memory")
#define CP_WAIT0()  asm volatile("cp.async.wait_group 0;\n" ::: "memory")

// EPI: 0 none, 1 = stage-1 epilogue (sigmoid for g/beta column ranges)
__device__ __forceinline__ float epi1(float v, int gc, const float* __restrict__ bias) {
    if (gc >= 1344 && gc < 2888) {
        float b = (gc < 2880) ? bias[gc - 1344] : 0.f;
        v = 1.f / (1.f + expf(-(v + b)));
    }
    return v;
}

// smem raw fp32 (A transposed+swizzled, B swizzled); cvt.rna.tf32 at fragment load.
template <int EPI>
__device__ __forceinline__ void tgemm_core(int N, int K,
                                           const float* __restrict__ A, int lda,
                                           const float* __restrict__ B, int ldb,
                                           const float* __restrict__ bias,
                                           float* __restrict__ C, int ldc,
                                           float* sA, float* sB) {
    const int tid  = threadIdx.x;             // 256 threads = 8 warps
    const int crow = blockIdx.y * BM;
    const int ccol = blockIdx.x * BN;

    const int wid  = tid >> 5;
    const int lane = tid & 31;
    const int lq   = lane >> 2;
    const int lr   = lane & 3;
    const int rm   = (wid & 1) * 32;   // 2 warps in M
    const int cn   = (wid >> 1) * 32;  // 4 warps in N

    const int am  = tid >> 2;          // 0..63
    const int ak4 = (tid & 3) * 4;     // 0,4,8,12
    const int bk  = tid >> 4;          // 0..15
    const int bc8 = (tid & 15) * 8;    // 0..120
    const int swb = (((bk & 3) ^ ((bk >> 2) & 3)) << 3);

    float acc[2][4][4] = {};
    float4 aR;

    // ---- prologue: tile 0 ----
    aR = *reinterpret_cast<const float4*>(&A[(long)(crow + am) * lda + ak4]);
    cp16(&sB[bk * BN + ((bc8) ^ swb)],     &B[(long)bk * ldb + ccol + bc8]);
    cp16(&sB[bk * BN + ((bc8 + 4) ^ swb)], &B[(long)bk * ldb + ccol + bc8 + 4]);
    CP_COMMIT();
    {
        const float av[4] = {aR.x, aR.y, aR.z, aR.w};
        #pragma unroll
        for (int i = 0; i < 4; ++i) {
            const int k  = ak4 + i;
            const int sw = (((k & 3) ^ ((k >> 2) & 3)) << 3);
            sA[k * BM + (am ^ sw)] = av[i];
        }
    }
    if (K > BK)
        aR = *reinterpret_cast<const float4*>(&A[(long)(crow + am) * lda + BK + ak4]);
    CP_WAIT0();
    __syncthreads();

    int buf = 0;
    for (int k0 = 0; k0 < K; k0 += BK, buf ^= 1) {
        float* cA = sA + buf * (BK * BM);
        float* cB = sB + buf * (BK * BN);
        const int nxt = buf ^ 1;

        // ---- issue next tile into the other buffer ----
        if (k0 + BK < K) {
            float* nB = sB + nxt * (BK * BN);
            cp16(&nB[bk * BN + ((bc8) ^ swb)],     &B[(long)(k0 + BK + bk) * ldb + ccol + bc8]);
            cp16(&nB[bk * BN + ((bc8 + 4) ^ swb)], &B[(long)(k0 + BK + bk) * ldb + ccol + bc8 + 4]);
            CP_COMMIT();
            float* nA = sA + nxt * (BK * BM);
            const float av[4] = {aR.x, aR.y, aR.z, aR.w};
            #pragma unroll
            for (int i = 0; i < 4; ++i) {
                const int k  = ak4 + i;
                const int sw = (((k & 3) ^ ((k >> 2) & 3)) << 3);
                nA[k * BM + (am ^ sw)] = av[i];
            }
            if (k0 + 2 * BK < K)
                aR = *reinterpret_cast<const float4*>(&A[(long)(crow + am) * lda + k0 + 2 * BK + ak4]);
        }

        // ---- compute on current buffer ----
        #pragma unroll
        for (int k8 = 0; k8 < BK; k8 += 8) {
            const int f0 = ((lr ^ (k8 >> 2)) & 3) << 3;
            const int f1 = f0 ^ 8;
            unsigned af[2][4], bf[4][2];
            #pragma unroll
            for (int mt = 0; mt < 2; ++mt) {
                const int r = rm + mt * 16 + lq;
                af[mt][0] = f2tf(cA[(k8 + lr) * BM + (r ^ f0)]);
                af[mt][1] = f2tf(cA[(k8 + lr) * BM + ((r + 8) ^ f0)]);
                af[mt][2] = f2tf(cA[(k8 + lr + 4) * BM + (r ^ f1)]);
                af[mt][3] = f2tf(cA[(k8 + lr + 4) * BM + ((r + 8) ^ f1)]);
            }
            #pragma unroll
            for (int nt = 0; nt < 4; ++nt) {
                const int c = cn + nt * 8 + lq;
                bf[nt][0] = f2tf(cB[(k8 + lr) * BN + (c ^ f0)]);
                bf[nt][1] = f2tf(cB[(k8 + lr + 4) * BN + (c ^ f1)]);
            }
            #pragma unroll
            for (int mt = 0; mt < 2; ++mt)
                #pragma unroll
                for (int nt = 0; nt < 4; ++nt)
                    mma_tf32(acc[mt][nt], af[mt], bf[nt]);
        }
        CP_WAIT0();
        __syncthreads();
    }

    #pragma unroll
    for (int mt = 0; mt < 2; ++mt) {
        const int row = crow + rm + mt * 16 + lq;
        #pragma unroll
        for (int nt = 0; nt < 4; ++nt) {
            const int col = ccol + cn + nt * 8 + lr * 2;
            float v0 = acc[mt][nt][0], v1 = acc[mt][nt][1];
            float v2 = acc[mt][nt][2], v3 = acc[mt][nt][3];
            if (EPI == 1) {
                v0 = epi1(v0, col, bias);     v1 = epi1(v1, col + 1, bias);
                v2 = epi1(v2, col, bias);     v3 = epi1(v3, col + 1, bias);
            }
            *reinterpret_cast<float2*>(&C[(long)row * ldc + col])       = make_float2(v0, v1);
            *reinterpret_cast<float2*>(&C[(long)(row + 8) * ldc + col]) = make_float2(v2, v3);
        }
    }
}

template <int EPI>
__global__ __launch_bounds__(256, 2)
void tgemm_kernel(int N, int K, const float* __restrict__ A, int lda,
                  const float* __restrict__ B, int ldb,
                  const float* __restrict__ bias, float* __restrict__ C, int ldc) {
    __shared__ float sA[2 * BK * BM];
    __shared__ float sB[2 * BK * BN];
    tgemm_core<EPI>(N, K, A, lda, B, ldb, bias, C, ldc, sA, sB);
}

__global__ __launch_bounds__(256, 2)
void tgemm_dual_kernel(int N0, int K0, const float* __restrict__ A0,
                       const float* __restrict__ B0, float* __restrict__ C0,
                       int N1, int K1, const float* __restrict__ A1,
                       const float* __restrict__ B1, float* __restrict__ C1) {
    __shared__ float sA[2 * BK * BM];
    __shared__ float sB[2 * BK * BN];
    if (blockIdx.z == 0) {
        if ((int)blockIdx.x * BN >= N0) return;
        tgemm_core<0>(N0, K0, A0, K0, B0, N0, nullptr, C0, N0, sA, sB);
    } else {
        tgemm_core<0>(N1, K1, A1, K1, B1, N1, nullptr, C1, N1, sA, sB);
    }
}

// ---------------- stage-1 weight concat ----------------
__global__ void concat_w(const float* __restrict__ wq_a,
                         const float* __restrict__ wkv_a,
                         const float* __restrict__ wg_w,
                         const float* __restrict__ wb,
                         float* __restrict__ Bc) {
    const int c = blockIdx.x * 128 + threadIdx.x;
    const int r = blockIdx.y;
    float v;
    if      (c < 768)  v = wq_a [r * 768  + c];
    else if (c < 1344) v = wkv_a[r * 576  + (c - 768)];
    else if (c < 2880) v = wg_w [r * 1536 + (c - 1344)];
    else if (c < 2888) v = wb   [r * 8    + (c - 2880)];
    else               v = 0.f;
    Bc[(long)r * NBIG + c] = v;
}

// ---------------- fused row RMS norms (q then kv) ----------------
__device__ __forceinline__ void rms_row(const float* __restrict__ row,
                                        const float* __restrict__ w,
                                        float* __restrict__ out, int n) {
    float ss = 0.f;
    for (int i = threadIdx.x; i < n; i += 256) {
        float v = row[i];
        ss += v * v;
    }
    #pragma unroll
    for (int off = 16; off; off >>= 1)
        ss += __shfl_xor_sync(0xffffffffu, ss, off);
    __shared__ float red[8];
    __shared__ float scale_s;
    const int wid = threadIdx.x >> 5;
    if ((threadIdx.x & 31) == 0) red[wid] = ss;
    __syncthreads();
    if (threadIdx.x == 0) {
        float tot = 0.f;
        #pragma unroll
        for (int i = 0; i < 8; ++i) tot += red[i];
        scale_s = rsqrtf(tot / (float)n + 1e-5f);
    }
    __syncthreads();
    const float sc = scale_s;
    for (int i = threadIdx.x; i < n; i += 256)
        out[i] = row[i] * sc * w[i];
    __syncthreads();   // shared red/scale reused by second call
}

__global__ void rms_fused(const float* __restrict__ big,
                          const float* __restrict__ qw,
                          const float* __restrict__ kvw,
                          float* __restrict__ qn,
                          float* __restrict__ kvn) {
    const int t = blockIdx.x;
    rms_row(big + (long)t * NBIG,       qw,  qn  + (long)t * QLR,  QLR);
    rms_row(big + (long)t * NBIG + 768, kvw, kvn + (long)t * KVLR, KVLR);
}

// ---------------- prep: l2norm q (in place, *DK^-0.5), build + l2norm k ----------------
__global__ void prep_kernel(float* __restrict__ q,
                            const float* __restrict__ kv,
                            const float* __restrict__ big,
                            float* __restrict__ kf) {
    const int t = blockIdx.x >> 3;
    const int h = blockIdx.x & 7;
    const int i = threadIdx.x;  // 0..191

    const int qidx = t * (HH * DK) + h * DK + i;
    const float qv = q[qidx];
    const float kvv = (i < 128) ? kv[t * (HH * 256) + h * 256 + i]
                                : big[(long)t * NBIG + 1280 + (i - 128)];

    float q2 = qv * qv, k2 = kvv * kvv;
    #pragma unroll
    for (int off = 16; off; off >>= 1) {
        q2 += __shfl_xor_sync(0xffffffffu, q2, off);
        k2 += __shfl_xor_sync(0xffffffffu, k2, off);
    }
    __shared__ float sq[6], sk[6];
    __shared__ float scl[2];
    const int wid = threadIdx.x >> 5;
    if ((threadIdx.x & 31) == 0) { sq[wid] = q2; sk[wid] = k2; }
    __syncthreads();
    if (threadIdx.x == 0) {
        float a = 0.f, b = 0.f;
        #pragma unroll
        for (int j = 0; j < 6; ++j) { a += sq[j]; b += sk[j]; }
        scl[0] = rsqrtf(a + 1e-6f) * 0.07216878364870322f;
        scl[1] = rsqrtf(b + 1e-6f);
    }
    __syncthreads();
    q[qidx] = qv * scl[0];
    kf[qidx] = kvv * scl[1];
}

// ---------------- KDA recurrence: warp per (h,v) column, distance-3 register prefetch ----
struct RecIn {
    float2 e0, e1, e2, k0, k1, k2, q0, q1, q2;
    float vt, bt;
};

__global__ __launch_bounds__(256)
void kda_rec(const float* __restrict__ qf,
             const float* __restrict__ kf,
             const float* __restrict__ big,
             const float* __restrict__ kv,
             float* __restrict__ o) {
    const int warp = (blockIdx.x * blockDim.x + threadIdx.x) >> 5;  // 0..1023
    const int lane = threadIdx.x & 31;
    const int h = warp >> 7;
    const int v = warp & 127;

    float s0 = 0.f, s1 = 0.f, s2 = 0.f, s3 = 0.f, s4 = 0.f, s5 = 0.f;
    const int kbase = h * DK + lane * 6;

    // loads wrap via &1023 past the sequence end; those buffers are never stepped.
    #define RLOAD(I, tt) do {                                                  \
        const int _t = (tt) & (TT - 1);                                        \
        const int rb = _t * (HH * DK) + kbase;                                 \
        const float* ep = big + (long)_t * NBIG + 1344 + kbase;                \
        (I).e0 = *(const float2*)(ep);     (I).e1 = *(const float2*)(ep + 2);  \
        (I).e2 = *(const float2*)(ep + 4);                                     \
        (I).k0 = *(const float2*)(kf + rb);     (I).k1 = *(const float2*)(kf + rb + 2); \
        (I).k2 = *(const float2*)(kf + rb + 4);                                \
        (I).q0 = *(const float2*)(qf + rb);     (I).q1 = *(const float2*)(qf + rb + 2); \
        (I).q2 = *(const float2*)(qf + rb + 4);                                \
        (I).vt = kv[_t * (HH * 256) + h * 256 + 128 + v];                      \
        (I).bt = big[(long)_t * NBIG + 2880 + h];                              \
    } while (0)

    #define RSTEP(I, t) do {                                                   \
        s0 *= (I).e0.x; s1 *= (I).e0.y; s2 *= (I).e1.x;                        \
        s3 *= (I).e1.y; s4 *= (I).e2.x; s5 *= (I).e2.y;                        \
        float kse = fmaf(s0, (I).k0.x, fmaf(s1, (I).k0.y, fmaf(s2, (I).k1.x,   \
                    fmaf(s3, (I).k1.y, fmaf(s4, (I).k2.x, s5 * (I).k2.y)))));  \
        float qse = fmaf(s0, (I).q0.x, fmaf(s1, (I).q0.y, fmaf(s2, (I).q1.x,   \
                    fmaf(s3, (I).q1.y, fmaf(s4, (I).q2.x, s5 * (I).q2.y)))));  \
        float qk  = fmaf((I).k0.x, (I).q0.x, fmaf((I).k0.y, (I).q0.y,          \
                    fmaf((I).k1.x, (I).q1.x, fmaf((I).k1.y, (I).q1.y,          \
                    fmaf((I).k2.x, (I).q2.x, (I).k2.y * (I).q2.y)))));         \
        _Pragma("unroll")                                                      \
        for (int off = 16; off; off >>= 1) {                                   \
            kse += __shfl_xor_sync(0xffffffffu, kse, off);                     \
            qse += __shfl_xor_sync(0xffffffffu, qse, off);                     \
            qk  += __shfl_xor_sync(0xffffffffu, qk,  off);                     \
        }                                                                      \
        const float u = (I).bt * ((I).vt - kse);                               \
        float ov = fmaf(qk, u, qse);                                           \
        s0 = fmaf((I).k0.x, u, s0); s1 = fmaf((I).k0.y, u, s1);                \
        s2 = fmaf((I).k1.x, u, s2); s3 = fmaf((I).k1.y, u, s3);                \
        s4 = fmaf((I).k2.x, u, s4); s5 = fmaf((I).k2.y, u, s5);                \
        if (lane == 0) {                                                       \
            if (ov != ov) ov = 0.f;                                            \
            ov = fminf(fmaxf(ov, -10000.f), 10000.f);                          \
            o[(t) * (HH * DV) + h * DV + v] = ov;                              \
        }                                                                      \
    } while (0)

    RecIn ia, ib, ic, id;
    RLOAD(ia, 0);
    RLOAD(ib, 1);
    RLOAD(ic, 2);
    for (int t = 0; t < TT; t += 4) {
        RLOAD(id, t + 3);
        RSTEP(ia, t);
        RLOAD(ia, t + 4);
        RSTEP(ib, t + 1);
        RLOAD(ib, t + 5);
        RSTEP(ic, t + 2);
        RLOAD(ic, t + 6);
        RSTEP(id, t + 3);
    }
    #undef RLOAD
    #undef RSTEP
}

// ---------------- launch ----------------
extern "C" void kernel_launch(void* const* d_in, const int* in_sizes, int n_in,
                              void* d_out, int out_size) {
    (void)in_sizes; (void)n_in; (void)out_size;
    const float* x         = (const float*)d_in[0];
    const float* wq_a      = (const float*)d_in[3];
    const float* q_norm_w  = (const float*)d_in[4];
    const float* wq_b      = (const float*)d_in[5];
    const float* wkv_a     = (const float*)d_in[6];
    const float* kv_norm_w = (const float*)d_in[7];
    const float* wkv_b     = (const float*)d_in[8];
    const float* wg_w      = (const float*)d_in[9];
    const float* wg_b      = (const float*)d_in[10];
    const float* wb        = (const float*)d_in[11];
    const float* wo        = (const float*)d_in[12];
    float* out = (float*)d_out;

    float *bc, *big, *qn, *kvn, *q, *kv, *kf, *ov;
    cudaGetSymbolAddress((void**)&bc,  d_bc);
    cudaGetSymbolAddress((void**)&big, d_big);
    cudaGetSymbolAddress((void**)&qn,  d_qn);
    cudaGetSymbolAddress((void**)&kvn, d_kvn);
    cudaGetSymbolAddress((void**)&q,   d_q);
    cudaGetSymbolAddress((void**)&kv,  d_kv);
    cudaGetSymbolAddress((void**)&kf,  d_kf);
    cudaGetSymbolAddress((void**)&ov,  d_ov);

    concat_w<<<dim3(NBIG / 128, DIMX), 128>>>(wq_a, wkv_a, wg_w, wb, bc);

    // Stage 1: big = x @ [wq_a | wkv_a | wg_w | wb] (+ sigmoid epilogues)
    tgemm_kernel<1><<<dim3(NBIG / BN, TT / BM), 256>>>(NBIG, DIMX, x, DIMX, bc, NBIG, wg_b, big, NBIG);

    // Stage 2: fused RMS norms
    rms_fused<<<TT, 256>>>(big, q_norm_w, kv_norm_w, qn, kvn);

    // Stage 3: batched up-projections
    tgemm_dual_kernel<<<dim3(2048 / BN, TT / BM, 2), 256>>>(
        1536, QLR,  qn,  wq_b,  q,
        2048, KVLR, kvn, wkv_b, kv);

    // Stage 4: l2norm q/k, assemble k
    prep_kernel<<<TT * HH, 192>>>(q, kv, big, kf);

    // Stage 5: sequential KDA recurrence (distance-3 register prefetch)
    kda_rec<<<128, 256>>>(q, kf, big, kv, ov);

    // Stage 6: output projection (plain TF32)
    tgemm_kernel<0><<<dim3(DIMX / BN, TT / BM), 256>>>(DIMX, DIMX, ov, DIMX, wo, DIMX, nullptr, out, DIMX);
}